// round 1
// baseline (speedup 1.0000x reference)
#include <cuda_runtime.h>
#include <math.h>

#define DEPTH 15
#define N_NODES ((1 << DEPTH) - 1)   // 32767
#define DD 512
#define HH 512
#define G4 (4 * HH)                  // 2048 gate columns: [i | f | o | u]

// ---------------- scratch (device globals; allocation-free) ----------------
__device__ float g_P[(size_t)N_NODES * G4];           // x-part + bias for all gates, all nodes (268 MB)
__device__ float g_G[(size_t)(1 << (DEPTH - 1)) * G4];// per-level child h-part (134 MB)
__device__ float g_h[(size_t)N_NODES * HH];           // 67 MB
__device__ float g_c[(size_t)N_NODES * HH];           // 67 MB
__device__ float g_Wx[(size_t)G4 * DD];               // packed x-columns of Wi,Wf,Wo,Wu
__device__ float g_Wh[(size_t)G4 * HH];               // packed h-columns
__device__ float g_b[G4];

// ---------------- fast activations ----------------
__device__ __forceinline__ float tanh_fast(float x) {
    float y;
    asm("tanh.approx.f32 %0, %1;" : "=f"(y) : "f"(x));
    return y;
}
__device__ __forceinline__ float sig_fast(float x) {
    return 0.5f * tanh_fast(0.5f * x) + 0.5f;
}

// ---------------- pack weights into [i|f|o|u] x/h halves ----------------
__global__ void pack_weights(const float* __restrict__ Wi, const float* __restrict__ bi,
                             const float* __restrict__ Wf, const float* __restrict__ bf,
                             const float* __restrict__ Wo, const float* __restrict__ bo,
                             const float* __restrict__ Wu, const float* __restrict__ bu) {
    int idx = blockIdx.x * blockDim.x + threadIdx.x;
    if (idx < G4 * DD) {
        int row = idx >> 9;        // gate-cat row 0..2047
        int col = idx & 511;       // k 0..511
        const float* W;
        int r = row & 511;
        int g = row >> 9;          // 0=i,1=f,2=o,3=u
        W = (g == 0) ? Wi : (g == 1) ? Wf : (g == 2) ? Wo : Wu;
        const float* src = W + (size_t)r * (DD + HH);
        g_Wx[idx] = src[col];
        g_Wh[idx] = src[DD + col];
    }
    if (idx < G4) {
        int g = idx >> 9, r = idx & 511;
        const float* b = (g == 0) ? bi : (g == 1) ? bf : (g == 2) ? bo : bu;
        g_b[idx] = b[r];
    }
}

// ---------------- C(M x 2048) = A(M x 512) @ W(2048 x 512)^T (+bias) ----------------
// classic 128x128x16 tiled sgemm, 256 threads, 8x8 per-thread microtile
template <bool ADD_BIAS>
__global__ __launch_bounds__(256) void gemm_nt(const float* __restrict__ A,
                                               const float* __restrict__ W,
                                               float* __restrict__ C, int M) {
    const int BM = 128, BN = 128, BK = 16;
    __shared__ float As[BK][BM + 4];
    __shared__ float Ws[BK][BN + 4];
    const int bm = blockIdx.y * BM;
    const int bn = blockIdx.x * BN;
    const int tid = threadIdx.x;
    const int tx = tid & 15;      // 0..15 -> 8 N-cols each
    const int ty = tid >> 4;      // 0..15 -> 8 M-rows each

    float acc[8][8];
#pragma unroll
    for (int i = 0; i < 8; i++)
#pragma unroll
        for (int j = 0; j < 8; j++) acc[i][j] = 0.f;

    for (int k0 = 0; k0 < DD; k0 += BK) {
        // load A slab (128x16) as 512 float4, 2 per thread, store transposed
#pragma unroll
        for (int i = 0; i < 2; i++) {
            int l = tid + i * 256;            // float4 index
            int row = l >> 2;                 // 4 float4 per row
            int kq = (l & 3) << 2;
            float4 v = make_float4(0.f, 0.f, 0.f, 0.f);
            if (bm + row < M)
                v = *(const float4*)(A + (size_t)(bm + row) * DD + k0 + kq);
            As[kq + 0][row] = v.x; As[kq + 1][row] = v.y;
            As[kq + 2][row] = v.z; As[kq + 3][row] = v.w;
        }
#pragma unroll
        for (int i = 0; i < 2; i++) {
            int l = tid + i * 256;
            int row = l >> 2;
            int kq = (l & 3) << 2;
            float4 v = *(const float4*)(W + (size_t)(bn + row) * DD + k0 + kq);
            Ws[kq + 0][row] = v.x; Ws[kq + 1][row] = v.y;
            Ws[kq + 2][row] = v.z; Ws[kq + 3][row] = v.w;
        }
        __syncthreads();
#pragma unroll
        for (int kk = 0; kk < BK; kk++) {
            float a[8], b[8];
#pragma unroll
            for (int i = 0; i < 8; i++) a[i] = As[kk][ty * 8 + i];
#pragma unroll
            for (int j = 0; j < 8; j++) b[j] = Ws[kk][tx * 8 + j];
#pragma unroll
            for (int i = 0; i < 8; i++)
#pragma unroll
                for (int j = 0; j < 8; j++) acc[i][j] += a[i] * b[j];
        }
        __syncthreads();
    }
#pragma unroll
    for (int i = 0; i < 8; i++) {
        int row = bm + ty * 8 + i;
        if (row < M) {
#pragma unroll
            for (int j = 0; j < 8; j++) {
                int col = bn + tx * 8 + j;
                float v = acc[i][j];
                if (ADD_BIAS) v += g_b[col];
                C[(size_t)row * G4 + col] = v;
            }
        }
    }
}

// ---------------- leaf level: h = 0 children ----------------
__global__ void leaf_kernel(int start, int cnt) {
    int idx = blockIdx.x * blockDim.x + threadIdx.x;
    if (idx >= cnt * HH) return;
    int b = idx >> 9, j = idx & 511;
    size_t n = (size_t)(start + b);
    const float* Pp = g_P + n * G4;
    float i = sig_fast(Pp[j]);
    float o = sig_fast(Pp[2 * HH + j]);
    float u = tanh_fast(Pp[3 * HH + j]);
    float c = i * u;
    g_c[n * HH + j] = c;
    g_h[n * HH + j] = o * tanh_fast(c);
}

// ---------------- internal level combine ----------------
__global__ void combine_kernel(int start, int cnt, int cs) {
    int idx = blockIdx.x * blockDim.x + threadIdx.x;
    if (idx >= cnt * HH) return;
    int b = idx >> 9, j = idx & 511;
    size_t n = (size_t)(start + b);
    const float* Pp = g_P + n * G4;
    const float* Gl = g_G + (size_t)(2 * b) * G4;
    const float* Gr = Gl + G4;
    float i  = sig_fast(Pp[j]            + Gl[j]            + Gr[j]);
    float fl = sig_fast(Pp[HH + j]       + Gl[HH + j]);
    float fr = sig_fast(Pp[HH + j]       + Gr[HH + j]);
    float o  = sig_fast(Pp[2 * HH + j]   + Gl[2 * HH + j]   + Gr[2 * HH + j]);
    float u  = tanh_fast(Pp[3 * HH + j]  + Gl[3 * HH + j]   + Gr[3 * HH + j]);
    float cl_ = g_c[(size_t)(cs + 2 * b) * HH + j];
    float cr_ = g_c[(size_t)(cs + 2 * b + 1) * HH + j];
    float c = i * u + fl * cl_ + fr * cr_;
    g_c[n * HH + j] = c;
    g_h[n * HH + j] = o * tanh_fast(c);
}

// ---------------- output: [h[0] | c[0]] ----------------
__global__ void write_out(float* __restrict__ out, int out_size) {
    int j = blockIdx.x * blockDim.x + threadIdx.x;
    if (j < HH && j < out_size) out[j] = g_h[j];
    int j2 = j + HH;
    if (j < HH && j2 < out_size) out[j2] = g_c[j];
}

extern "C" void kernel_launch(void* const* d_in, const int* in_sizes, int n_in,
                              void* d_out, int out_size) {
    const float* x  = (const float*)d_in[0];
    const float* Wi = (const float*)d_in[1];
    const float* bi = (const float*)d_in[2];
    const float* Wf = (const float*)d_in[3];
    const float* bf = (const float*)d_in[4];
    const float* Wo = (const float*)d_in[5];
    const float* bo = (const float*)d_in[6];
    const float* Wu = (const float*)d_in[7];
    const float* bu = (const float*)d_in[8];
    float* out = (float*)d_out;

    // resolve device-global addresses (pure queries; capture-safe)
    float *pP, *pG, *ph, *pWx, *pWh;
    cudaGetSymbolAddress((void**)&pP,  g_P);
    cudaGetSymbolAddress((void**)&pG,  g_G);
    cudaGetSymbolAddress((void**)&ph,  g_h);
    cudaGetSymbolAddress((void**)&pWx, g_Wx);
    cudaGetSymbolAddress((void**)&pWh, g_Wh);

    pack_weights<<<(G4 * DD + 255) / 256, 256>>>(Wi, bi, Wf, bf, Wo, bo, Wu, bu);

    // P = x @ Wx_cat^T + b_cat  for all nodes at once
    {
        dim3 grid(G4 / 128, (N_NODES + 127) / 128);
        gemm_nt<true><<<grid, 256>>>(x, pWx, pP, N_NODES);
    }

    // leaves (lvl = DEPTH-1)
    {
        int start = (1 << (DEPTH - 1)) - 1;
        int cnt = 1 << (DEPTH - 1);
        leaf_kernel<<<(cnt * HH + 255) / 256, 256>>>(start, cnt);
    }

    // internal levels
    for (int lvl = DEPTH - 2; lvl >= 0; lvl--) {
        int start = (1 << lvl) - 1;
        int cnt = 1 << lvl;
        int cs = 2 * start + 1;
        int M = 2 * cnt;
        dim3 grid(G4 / 128, (M + 127) / 128);
        gemm_nt<false><<<grid, 256>>>(ph + (size_t)cs * HH, pWh, pG, M);
        combine_kernel<<<(cnt * HH + 255) / 256, 256>>>(start, cnt, cs);
    }

    write_out<<<(2 * HH + 255) / 256, 256>>>(out, out_size);
}

// round 3
// speedup vs baseline: 2.9541x; 2.9541x over previous
#include <cuda_runtime.h>
#include <cstdint>
#include <stdint.h>
#include <math.h>

#define DEPTH 15
#define N_NODES ((1 << DEPTH) - 1)   // 32767
#define DD 512
#define HH 512
#define G4 (4 * HH)                  // 2048 gate columns: [i | f | o | u]

// ---------------- scratch (device globals; allocation-free) ----------------
__device__ float g_P[(size_t)N_NODES * G4];            // x-part + bias for all gates (268 MB)
__device__ float g_G[(size_t)(1 << (DEPTH - 1)) * G4]; // per-level child h-part (134 MB)
__device__ float g_h[(size_t)N_NODES * HH];
__device__ float g_c[(size_t)N_NODES * HH];
__device__ float g_Wx[(size_t)G4 * DD];                // packed x-columns (tf32-rounded)
__device__ float g_Wh[(size_t)G4 * HH];                // packed h-columns (tf32-rounded)
__device__ float g_b[G4];

// ---------------- fast activations ----------------
__device__ __forceinline__ float tanh_fast(float x) {
    float y;
    asm("tanh.approx.f32 %0, %1;" : "=f"(y) : "f"(x));
    return y;
}
__device__ __forceinline__ float sig_fast(float x) {
    return 0.5f * tanh_fast(0.5f * x) + 0.5f;
}
__device__ __forceinline__ float to_tf32(float x) {
    unsigned int r;
    asm("cvt.rna.tf32.f32 %0, %1;" : "=r"(r) : "f"(x));
    return __uint_as_float(r);
}

// ---------------- pack weights into [i|f|o|u] x/h halves (tf32-rounded) ------
__global__ void pack_weights(const float* __restrict__ Wi, const float* __restrict__ bi,
                             const float* __restrict__ Wf, const float* __restrict__ bf,
                             const float* __restrict__ Wo, const float* __restrict__ bo,
                             const float* __restrict__ Wu, const float* __restrict__ bu) {
    int idx = blockIdx.x * blockDim.x + threadIdx.x;
    if (idx < G4 * DD) {
        int row = idx >> 9;
        int col = idx & 511;
        int r = row & 511;
        int g = row >> 9;
        const float* W = (g == 0) ? Wi : (g == 1) ? Wf : (g == 2) ? Wo : Wu;
        const float* src = W + (size_t)r * (DD + HH);
        g_Wx[idx] = to_tf32(src[col]);
        g_Wh[idx] = to_tf32(src[DD + col]);
    }
    if (idx < G4) {
        int g = idx >> 9, r = idx & 511;
        const float* b = (g == 0) ? bi : (g == 1) ? bf : (g == 2) ? bo : bu;
        g_b[idx] = b[r];
    }
}

// ---------------- tf32 tensor-core GEMM ----------------
// C(M x 2048) = A(M x 512) @ W(2048 x 512)^T (+bias)
// block tile 128x128x32, 8 warps (2 m x 4 n), warp tile 64x32, mma m16n8k8
#define SM_STRIDE 36   // floats per smem row: (4*g + tig) banks unique per lane -> conflict-free

template <bool ADD_BIAS>
__global__ __launch_bounds__(256) void gemm_tc(const float* __restrict__ A,
                                               const float* __restrict__ W,
                                               float* __restrict__ C, int M) {
    __shared__ float As[128 * SM_STRIDE];
    __shared__ float Ws[128 * SM_STRIDE];

    const int bm = blockIdx.y * 128;
    const int bn = blockIdx.x * 128;
    const int tid = threadIdx.x;
    const int lane = tid & 31;
    const int wid = tid >> 5;
    const int wm = (wid >> 2) << 6;   // 0 / 64
    const int wn = (wid & 3) << 5;    // 0 / 32 / 64 / 96
    const int g = lane >> 2;          // 0..7
    const int tig = lane & 3;         // 0..3

    float acc[4][4][4];
#pragma unroll
    for (int mt = 0; mt < 4; mt++)
#pragma unroll
        for (int nt = 0; nt < 4; nt++)
#pragma unroll
            for (int r = 0; r < 4; r++) acc[mt][nt][r] = 0.f;

    for (int k0 = 0; k0 < DD; k0 += 32) {
        // global -> shared (tf32-rounded); 1024 float4 total, 4 per thread
#pragma unroll
        for (int i = 0; i < 4; i++) {
            int id = tid + i * 256;          // 0..1023
            int row = id >> 3;               // 0..127
            int kq = (id & 7) << 2;          // 0,4,...,28
            float4 v = make_float4(0.f, 0.f, 0.f, 0.f);
            if (bm + row < M)
                v = *(const float4*)(A + (size_t)(bm + row) * DD + k0 + kq);
            float4 w = *(const float4*)(W + (size_t)(bn + row) * DD + k0 + kq);
            v.x = to_tf32(v.x); v.y = to_tf32(v.y); v.z = to_tf32(v.z); v.w = to_tf32(v.w);
            *(float4*)(As + row * SM_STRIDE + kq) = v;
            *(float4*)(Ws + row * SM_STRIDE + kq) = w;   // W pre-rounded at pack
        }
        __syncthreads();

#pragma unroll
        for (int ks = 0; ks < 4; ks++) {
            const int kk = ks << 3;
            unsigned int a[4][4];
#pragma unroll
            for (int mt = 0; mt < 4; mt++) {
                int m = wm + (mt << 4) + g;
                a[mt][0] = __float_as_uint(As[m * SM_STRIDE + kk + tig]);
                a[mt][1] = __float_as_uint(As[(m + 8) * SM_STRIDE + kk + tig]);
                a[mt][2] = __float_as_uint(As[m * SM_STRIDE + kk + tig + 4]);
                a[mt][3] = __float_as_uint(As[(m + 8) * SM_STRIDE + kk + tig + 4]);
            }
            unsigned int b[4][2];
#pragma unroll
            for (int nt = 0; nt < 4; nt++) {
                int n = wn + (nt << 3) + g;
                b[nt][0] = __float_as_uint(Ws[n * SM_STRIDE + kk + tig]);
                b[nt][1] = __float_as_uint(Ws[n * SM_STRIDE + kk + tig + 4]);
            }
#pragma unroll
            for (int mt = 0; mt < 4; mt++)
#pragma unroll
                for (int nt = 0; nt < 4; nt++) {
                    float* c = acc[mt][nt];
                    asm volatile(
                        "mma.sync.aligned.m16n8k8.row.col.f32.tf32.tf32.f32 "
                        "{%0,%1,%2,%3}, {%4,%5,%6,%7}, {%8,%9}, {%0,%1,%2,%3};"
                        : "+f"(c[0]), "+f"(c[1]), "+f"(c[2]), "+f"(c[3])
                        : "r"(a[mt][0]), "r"(a[mt][1]), "r"(a[mt][2]), "r"(a[mt][3]),
                          "r"(b[nt][0]), "r"(b[nt][1]));
                }
        }
        __syncthreads();
    }

    // epilogue: C fragment c0,c1 at (row=g, col=2*tig,2*tig+1), c2,c3 at row=g+8
#pragma unroll
    for (int mt = 0; mt < 4; mt++) {
        int row0 = bm + wm + (mt << 4) + g;
#pragma unroll
        for (int nt = 0; nt < 4; nt++) {
            int col = bn + wn + (nt << 3) + (tig << 1);
            float b0 = 0.f, b1 = 0.f;
            if (ADD_BIAS) { b0 = g_b[col]; b1 = g_b[col + 1]; }
            if (row0 < M) {
                C[(size_t)row0 * G4 + col]     = acc[mt][nt][0] + b0;
                C[(size_t)row0 * G4 + col + 1] = acc[mt][nt][1] + b1;
            }
            if (row0 + 8 < M) {
                C[(size_t)(row0 + 8) * G4 + col]     = acc[mt][nt][2] + b0;
                C[(size_t)(row0 + 8) * G4 + col + 1] = acc[mt][nt][3] + b1;
            }
        }
    }
}

// ---------------- leaf level: h = 0 children ----------------
__global__ void leaf_kernel(int start, int cnt) {
    int idx = blockIdx.x * blockDim.x + threadIdx.x;
    if (idx >= cnt * HH) return;
    int b = idx >> 9, j = idx & 511;
    size_t n = (size_t)(start + b);
    const float* Pp = g_P + n * G4;
    float i = sig_fast(Pp[j]);
    float o = sig_fast(Pp[2 * HH + j]);
    float u = tanh_fast(Pp[3 * HH + j]);
    float c = i * u;
    g_c[n * HH + j] = c;
    g_h[n * HH + j] = o * tanh_fast(c);
}

// ---------------- internal level combine ----------------
__global__ void combine_kernel(int start, int cnt, int cs) {
    int idx = blockIdx.x * blockDim.x + threadIdx.x;
    if (idx >= cnt * HH) return;
    int b = idx >> 9, j = idx & 511;
    size_t n = (size_t)(start + b);
    const float* Pp = g_P + n * G4;
    const float* Gl = g_G + (size_t)(2 * b) * G4;
    const float* Gr = Gl + G4;
    float i  = sig_fast(Pp[j]           + Gl[j]           + Gr[j]);
    float fl = sig_fast(Pp[HH + j]      + Gl[HH + j]);
    float fr = sig_fast(Pp[HH + j]      + Gr[HH + j]);
    float o  = sig_fast(Pp[2 * HH + j]  + Gl[2 * HH + j]  + Gr[2 * HH + j]);
    float u  = tanh_fast(Pp[3 * HH + j] + Gl[3 * HH + j]  + Gr[3 * HH + j]);
    float cl_ = g_c[(size_t)(cs + 2 * b) * HH + j];
    float cr_ = g_c[(size_t)(cs + 2 * b + 1) * HH + j];
    float c = i * u + fl * cl_ + fr * cr_;
    g_c[n * HH + j] = c;
    g_h[n * HH + j] = o * tanh_fast(c);
}

// ---------------- output: [h[0] | c[0]] ----------------
__global__ void write_out(float* __restrict__ out, int out_size) {
    int j = blockIdx.x * blockDim.x + threadIdx.x;
    if (j < HH && j < out_size) out[j] = g_h[j];
    int j2 = j + HH;
    if (j < HH && j2 < out_size) out[j2] = g_c[j];
}

extern "C" void kernel_launch(void* const* d_in, const int* in_sizes, int n_in,
                              void* d_out, int out_size) {
    const float* x  = (const float*)d_in[0];
    const float* Wi = (const float*)d_in[1];
    const float* bi = (const float*)d_in[2];
    const float* Wf = (const float*)d_in[3];
    const float* bf = (const float*)d_in[4];
    const float* Wo = (const float*)d_in[5];
    const float* bo = (const float*)d_in[6];
    const float* Wu = (const float*)d_in[7];
    const float* bu = (const float*)d_in[8];
    float* out = (float*)d_out;

    float *pP, *pG, *ph, *pWx, *pWh;
    cudaGetSymbolAddress((void**)&pP,  g_P);
    cudaGetSymbolAddress((void**)&pG,  g_G);
    cudaGetSymbolAddress((void**)&ph,  g_h);
    cudaGetSymbolAddress((void**)&pWx, g_Wx);
    cudaGetSymbolAddress((void**)&pWh, g_Wh);

    pack_weights<<<(G4 * DD + 255) / 256, 256>>>(Wi, bi, Wf, bf, Wo, bo, Wu, bu);

    // P = x @ Wx_cat^T + b_cat  for all nodes at once
    {
        dim3 grid(G4 / 128, (N_NODES + 127) / 128);
        gemm_tc<true><<<grid, 256>>>(x, pWx, pP, N_NODES);
    }

    // leaves (lvl = DEPTH-1)
    {
        int start = (1 << (DEPTH - 1)) - 1;
        int cnt = 1 << (DEPTH - 1);
        leaf_kernel<<<(cnt * HH + 255) / 256, 256>>>(start, cnt);
    }

    // internal levels
    for (int lvl = DEPTH - 2; lvl >= 0; lvl--) {
        int start = (1 << lvl) - 1;
        int cnt = 1 << lvl;
        int cs = 2 * start + 1;
        int M = 2 * cnt;
        dim3 grid(G4 / 128, (M + 127) / 128);
        gemm_tc<false><<<grid, 256>>>(ph + (size_t)cs * HH, pWh, pG, M);
        combine_kernel<<<(cnt * HH + 255) / 256, 256>>>(start, cnt, cs);
    }

    write_out<<<(2 * HH + 255) / 256, 256>>>(out, out_size);
}